// round 9
// baseline (speedup 1.0000x reference)
#include <cuda_runtime.h>
#include <cuda_fp16.h>
#include <math.h>

#define NNODES 100000
#define NPAD   100096
#define FIN    128
#define HID    256
#define NCLS   40
#define EMAX   1600000

// ---------------- scratch ----------------
__device__ __half g_bufA[(size_t)NPAD * HID];
__device__ __half g_bufB[(size_t)NPAD * HID];
__device__ __half g_W1T[256 * 128];
__device__ __half g_W2T[256 * 256];
__device__ __half g_W3T[256 * 256];
__device__ float g_dinv[NNODES];
__device__ int   g_hist[NNODES];
__device__ int   g_rowptr[NNODES + 1];
__device__ int   g_fill[NNODES];
__device__ int   g_col[EMAX];

__device__ __forceinline__ __half* selbuf(int s) { return s ? g_bufB : g_bufA; }

__device__ __forceinline__ void h8_to_f8(uint4 v, float* f) {
    const __half2* h = reinterpret_cast<const __half2*>(&v);
#pragma unroll
    for (int k = 0; k < 4; k++) {
        float2 t = __half22float2(h[k]);
        f[2 * k] = t.x;
        f[2 * k + 1] = t.y;
    }
}
__device__ __forceinline__ uint4 f8_to_h8(const float* f) {
    uint4 o;
    __half2* h = reinterpret_cast<__half2*>(&o);
#pragma unroll
    for (int k = 0; k < 4; k++) h[k] = __floats2half2_rn(f[2 * k], f[2 * k + 1]);
    return o;
}

// ---------------- precompute ----------------
__global__ void k_init() {
    int i = blockIdx.x * blockDim.x + threadIdx.x;
    if (i < NNODES) g_hist[i] = 0;
}

__global__ void k_hist(const int* __restrict__ ei, int E) {
    int e = blockIdx.x * blockDim.x + threadIdx.x;
    if (e < E) atomicAdd(&g_hist[ei[E + e]], 1);
}

__global__ void k_dinv() {
    int i = blockIdx.x * blockDim.x + threadIdx.x;
    if (i < NNODES) g_dinv[i] = rsqrtf((float)(g_hist[i] + 1));
}

__global__ void k_scan(int n, int total_edges) {
    __shared__ int s[1024];
    const int t = threadIdx.x;
    const int C = (n + 1023) >> 10;
    const int lo = t * C;
    const int hi = (lo + C < n) ? lo + C : n;
    int sum = 0;
    for (int i = lo; i < hi; i++) sum += g_hist[i];
    s[t] = sum;
    __syncthreads();
    for (int off = 1; off < 1024; off <<= 1) {
        int v = (t >= off) ? s[t - off] : 0;
        __syncthreads();
        s[t] += v;
        __syncthreads();
    }
    int run = (t == 0) ? 0 : s[t - 1];
    for (int i = lo; i < hi; i++) {
        g_rowptr[i] = run;
        g_fill[i] = run;
        run += g_hist[i];
    }
    if (t == 1023) g_rowptr[n] = total_edges;
}

__global__ void k_scatter(const int* __restrict__ ei, int E) {
    int e = blockIdx.x * blockDim.x + threadIdx.x;
    if (e < E) {
        int d = ei[E + e];
        int pos = atomicAdd(&g_fill[d], 1);
        g_col[pos] = ei[e];
    }
}

// fp32 weights [K,256] -> fp16 WT[n][k], k-permuted per 16-group for HMMA B frags
__global__ void k_wconv(const float* __restrict__ W1, const float* __restrict__ W2,
                        const float* __restrict__ W3) {
    int i = blockIdx.x * blockDim.x + threadIdx.x;
    if (i < 256 * 256) {
        int n = i >> 8, k = i & 255;
        int ko = (k & ~15) + 2 * ((k >> 2) & 3) + (k & 1) + (((k >> 1) & 1) << 3);
        g_W2T[n * 256 + k] = __float2half(W2[ko * 256 + n]);
        g_W3T[n * 256 + k] = __float2half(W3[ko * 256 + n]);
    }
    if (i < 256 * 128) {
        int n = i >> 7, k = i & 127;
        int ko = (k & ~15) + 2 * ((k >> 2) & 3) + (k & 1) + (((k >> 1) & 1) << 3);
        g_W1T[n * 128 + k] = __float2half(W1[ko * 256 + n]);
    }
}

// x fp32 -> fp16 (streamed, once)
__global__ void k_xconv(const float* __restrict__ x, int dst_sel) {
    int i = blockIdx.x * blockDim.x + threadIdx.x;
    if (i < NNODES * (FIN / 4)) {
        float4 v = reinterpret_cast<const float4*>(x)[i];
        uint2 o;
        __half2* oh = reinterpret_cast<__half2*>(&o);
        oh[0] = __floats2half2_rn(v.x, v.y);
        oh[1] = __floats2half2_rn(v.z, v.w);
        reinterpret_cast<uint2*>(selbuf(dst_sel))[i] = o;
    }
}

// ---------------- agg conv1: gather fp16 (F=128) ----------------
__global__ void k_agg_x_h(int src_sel, int dst_sel) {
    const __half* in = selbuf(src_sel);
    __half* out = selbuf(dst_sel);
    const int wid = (blockIdx.x * blockDim.x + threadIdx.x) >> 5;
    if (wid >= NNODES) return;
    const int lane = threadIdx.x & 31;
    const int coff = lane * 4;

    float acc[4] = {0.f, 0.f, 0.f, 0.f};
    const int beg = g_rowptr[wid];
    const int end = g_rowptr[wid + 1];
    for (int base = beg; base < end; base += 32) {
        const int nrem = end - base;
        int idx = 0;
        float w = 0.f;
        if (lane < nrem) {
            idx = g_col[base + lane];
            w = g_dinv[idx];
        }
        const int m = nrem < 32 ? nrem : 32;
        int j = 0;
        for (; j + 2 <= m; j += 2) {
            const int s0 = __shfl_sync(0xffffffffu, idx, j);
            const int s1 = __shfl_sync(0xffffffffu, idx, j + 1);
            const float w0 = __shfl_sync(0xffffffffu, w, j);
            const float w1 = __shfl_sync(0xffffffffu, w, j + 1);
            uint2 v0 = *reinterpret_cast<const uint2*>(in + (size_t)s0 * FIN + coff);
            uint2 v1 = *reinterpret_cast<const uint2*>(in + (size_t)s1 * FIN + coff);
            const __half2* h0 = reinterpret_cast<const __half2*>(&v0);
            const __half2* h1 = reinterpret_cast<const __half2*>(&v1);
#pragma unroll
            for (int k = 0; k < 2; k++) {
                float2 a = __half22float2(h0[k]);
                float2 b = __half22float2(h1[k]);
                acc[2 * k] += w0 * a.x + w1 * b.x;
                acc[2 * k + 1] += w0 * a.y + w1 * b.y;
            }
        }
        for (; j < m; j++) {
            const int s = __shfl_sync(0xffffffffu, idx, j);
            const float ww = __shfl_sync(0xffffffffu, w, j);
            uint2 v = *reinterpret_cast<const uint2*>(in + (size_t)s * FIN + coff);
            const __half2* h = reinterpret_cast<const __half2*>(&v);
#pragma unroll
            for (int k = 0; k < 2; k++) {
                float2 a = __half22float2(h[k]);
                acc[2 * k] += ww * a.x;
                acc[2 * k + 1] += ww * a.y;
            }
        }
    }
    const float di = g_dinv[wid];
    {
        uint2 v = *reinterpret_cast<const uint2*>(in + (size_t)wid * FIN + coff);
        const __half2* h = reinterpret_cast<const __half2*>(&v);
#pragma unroll
        for (int k = 0; k < 2; k++) {
            float2 a = __half22float2(h[k]);
            acc[2 * k] += di * a.x;
            acc[2 * k + 1] += di * a.y;
        }
    }
    uint2 o;
    __half2* oh = reinterpret_cast<__half2*>(&o);
    oh[0] = __floats2half2_rn(di * acc[0], di * acc[1]);
    oh[1] = __floats2half2_rn(di * acc[2], di * acc[3]);
    *reinterpret_cast<uint2*>(out + (size_t)wid * FIN + coff) = o;
}

// ---------------- agg mid layers: gather half F=256, +bias+relu ----------------
__global__ void k_agg_h256(int src_sel, int dst_sel, const float* __restrict__ bias) {
    const __half* in = selbuf(src_sel);
    __half* out = selbuf(dst_sel);
    const int wid = (blockIdx.x * blockDim.x + threadIdx.x) >> 5;
    if (wid >= NNODES) return;
    const int lane = threadIdx.x & 31;
    const int coff = lane * 8;

    float acc[8];
#pragma unroll
    for (int i = 0; i < 8; i++) acc[i] = 0.f;

    const int beg = g_rowptr[wid];
    const int end = g_rowptr[wid + 1];
    for (int base = beg; base < end; base += 32) {
        const int nrem = end - base;
        int idx = 0;
        float w = 0.f;
        if (lane < nrem) {
            idx = g_col[base + lane];
            w = g_dinv[idx];
        }
        const int m = nrem < 32 ? nrem : 32;
        int j = 0;
        for (; j + 2 <= m; j += 2) {
            const int s0 = __shfl_sync(0xffffffffu, idx, j);
            const int s1 = __shfl_sync(0xffffffffu, idx, j + 1);
            const float w0 = __shfl_sync(0xffffffffu, w, j);
            const float w1 = __shfl_sync(0xffffffffu, w, j + 1);
            uint4 v0 = *reinterpret_cast<const uint4*>(in + (size_t)s0 * HID + coff);
            uint4 v1 = *reinterpret_cast<const uint4*>(in + (size_t)s1 * HID + coff);
            float f0[8], f1[8];
            h8_to_f8(v0, f0);
            h8_to_f8(v1, f1);
#pragma unroll
            for (int i = 0; i < 8; i++) acc[i] += w0 * f0[i] + w1 * f1[i];
        }
        for (; j < m; j++) {
            const int s = __shfl_sync(0xffffffffu, idx, j);
            const float ww = __shfl_sync(0xffffffffu, w, j);
            uint4 v = *reinterpret_cast<const uint4*>(in + (size_t)s * HID + coff);
            float f[8];
            h8_to_f8(v, f);
#pragma unroll
            for (int i = 0; i < 8; i++) acc[i] += ww * f[i];
        }
    }
    const float di = g_dinv[wid];
    {
        uint4 v = *reinterpret_cast<const uint4*>(in + (size_t)wid * HID + coff);
        float f[8];
        h8_to_f8(v, f);
#pragma unroll
        for (int i = 0; i < 8; i++) acc[i] += di * f[i];
    }
    float r[8];
#pragma unroll
    for (int i = 0; i < 8; i++) {
        r[i] = fmaxf(di * acc[i] + bias[coff + i], 0.f);
    }
    *reinterpret_cast<uint4*>(out + (size_t)wid * HID + coff) = f8_to_h8(r);
}

// ---------------- final: gather half F=40, +bias, log_softmax ----------------
__global__ void k_agg40_lsm(int src_sel, float* __restrict__ out,
                            const float* __restrict__ bias) {
    const __half* in = selbuf(src_sel);
    const int wid = (blockIdx.x * blockDim.x + threadIdx.x) >> 5;
    if (wid >= NNODES) return;
    const int lane = threadIdx.x & 31;
    const bool has2 = lane < (NCLS - 32);

    float a0 = 0.f, a1 = 0.f;
    const int beg = g_rowptr[wid];
    const int end = g_rowptr[wid + 1];
    for (int base = beg; base < end; base += 32) {
        const int nrem = end - base;
        int idx = 0;
        float w = 0.f;
        if (lane < nrem) {
            idx = g_col[base + lane];
            w = g_dinv[idx];
        }
        const int m = nrem < 32 ? nrem : 32;
        for (int j = 0; j < m; j++) {
            const int s = __shfl_sync(0xffffffffu, idx, j);
            const float ww = __shfl_sync(0xffffffffu, w, j);
            a0 += ww * __half2float(in[(size_t)s * NCLS + lane]);
            if (has2) a1 += ww * __half2float(in[(size_t)s * NCLS + 32 + lane]);
        }
    }
    const float di = g_dinv[wid];
    a0 += di * __half2float(in[(size_t)wid * NCLS + lane]);
    if (has2) a1 += di * __half2float(in[(size_t)wid * NCLS + 32 + lane]);

    a0 = di * a0 + bias[lane];
    a1 = has2 ? (di * a1 + bias[32 + lane]) : -INFINITY;

    float mx = fmaxf(a0, a1);
#pragma unroll
    for (int off = 16; off; off >>= 1) mx = fmaxf(mx, __shfl_xor_sync(0xffffffffu, mx, off));
    float se = expf(a0 - mx) + (has2 ? expf(a1 - mx) : 0.f);
#pragma unroll
    for (int off = 16; off; off >>= 1) se += __shfl_xor_sync(0xffffffffu, se, off);
    const float lse = logf(se) + mx;

    out[(size_t)wid * NCLS + lane] = a0 - lse;
    if (has2) out[(size_t)wid * NCLS + 32 + lane] = a1 - lse;
}

// ---------------- tensor-core GEMM: block M64 x N256 (A read once) ----------------
template <int K, bool EPI>
__global__ __launch_bounds__(256) void k_gemm_mma(int src_sel, int wsel,
                                                  const float* __restrict__ bias, int dst_sel) {
    const __half* A = selbuf(src_sel);
    __half* C = selbuf(dst_sel);
    const __half* WT = (wsel == 1) ? g_W1T : (wsel == 2) ? g_W2T : g_W3T;

    const int tid = threadIdx.x;
    const int wid = tid >> 5;
    const int lane = tid & 31;
    const int gid = lane >> 2;
    const int tig = lane & 3;
    const int mbase = blockIdx.x * 64 + (wid & 1) * 32;
    const int nbase = (wid >> 1) * 64;

    float c[2][8][4];
#pragma unroll
    for (int i = 0; i < 2; i++)
#pragma unroll
        for (int j = 0; j < 8; j++)
#pragma unroll
            for (int q = 0; q < 4; q++) c[i][j][q] = 0.f;

#pragma unroll 4
    for (int kg = 0; kg < K / 16; kg++) {
        const int k0 = kg * 16;
        unsigned a[2][4];
#pragma unroll
        for (int i = 0; i < 2; i++) {
            const __half* ap = A + (size_t)(mbase + i * 16 + gid) * K + k0 + 2 * tig;
            a[i][0] = *reinterpret_cast<const unsigned*>(ap);
            a[i][1] = *reinterpret_cast<const unsigned*>(ap + 8 * K);
            a[i][2] = *reinterpret_cast<const unsigned*>(ap + 8);
            a[i][3] = *reinterpret_cast<const unsigned*>(ap + 8 * K + 8);
        }
#pragma unroll
        for (int j = 0; j < 8; j++) {
            const uint2 b = *reinterpret_cast<const uint2*>(
                WT + (size_t)(nbase + j * 8 + gid) * K + k0 + tig * 4);
#pragma unroll
            for (int i = 0; i < 2; i++) {
                asm volatile(
                    "mma.sync.aligned.m16n8k16.row.col.f32.f16.f16.f32 "
                    "{%0,%1,%2,%3}, {%4,%5,%6,%7}, {%8,%9}, {%0,%1,%2,%3};"
                    : "+f"(c[i][j][0]), "+f"(c[i][j][1]), "+f"(c[i][j][2]), "+f"(c[i][j][3])
                    : "r"(a[i][0]), "r"(a[i][1]), "r"(a[i][2]), "r"(a[i][3]),
                      "r"(b.x), "r"(b.y));
            }
        }
    }

#pragma unroll
    for (int i = 0; i < 2; i++) {
        const int r0 = mbase + i * 16 + gid;
#pragma unroll
        for (int j = 0; j < 8; j++) {
            const int col = nbase + j * 8 + 2 * tig;
            float v0 = c[i][j][0], v1 = c[i][j][1], v2 = c[i][j][2], v3 = c[i][j][3];
            if (EPI) {
                const float bz0 = bias[col];
                const float bz1 = bias[col + 1];
                v0 = fmaxf(v0 + bz0, 0.f); v1 = fmaxf(v1 + bz1, 0.f);
                v2 = fmaxf(v2 + bz0, 0.f); v3 = fmaxf(v3 + bz1, 0.f);
            }
            if (r0 < NNODES)
                *reinterpret_cast<__half2*>(C + (size_t)r0 * HID + col) = __floats2half2_rn(v0, v1);
            if (r0 + 8 < NNODES)
                *reinterpret_cast<__half2*>(C + (size_t)(r0 + 8) * HID + col) = __floats2half2_rn(v2, v3);
        }
    }
}

// ---------------- small GEMM: C_half[M,40] = A_half[M,256] @ W_f32[256,40] ----------------
__global__ void k_gemm_small(int src_sel, const float* __restrict__ W, int dst_sel) {
    const __half* A = selbuf(src_sel);
    __half* C = selbuf(dst_sel);
    constexpr int K = HID, NOUT = NCLS;
    constexpr int BM = 128, BN = 64, BK = 32;
    __shared__ float As[BK][BM];
    __shared__ float Bs[BK][BN];
    const int tid = threadIdx.x;
    const int tx = tid & 15;
    const int ty = tid >> 4;
    const int m0 = blockIdx.x * BM;

    float acc[8][4];
#pragma unroll
    for (int i = 0; i < 8; i++)
#pragma unroll
        for (int j = 0; j < 4; j++) acc[i][j] = 0.f;

    for (int k0 = 0; k0 < K; k0 += BK) {
#pragma unroll
        for (int l = 0; l < 2; l++) {
            const int lin = tid + l * 256;
            const int r = lin >> 2;
            const int c8 = lin & 3;
            uint4 v = make_uint4(0, 0, 0, 0);
            const int gr = m0 + r;
            if (gr < NNODES)
                v = __ldcs(reinterpret_cast<const uint4*>(A + (size_t)gr * K + k0 + c8 * 8));
            float f[8];
            h8_to_f8(v, f);
#pragma unroll
            for (int i = 0; i < 8; i++) As[c8 * 8 + i][r] = f[i];
        }
#pragma unroll
        for (int l = 0; l < 2; l++) {
            const int lin = tid + l * 256;
            const int r = lin >> 4;
            const int c4 = lin & 15;
            float4 v = make_float4(0.f, 0.f, 0.f, 0.f);
            const int gc = c4 * 4;
            if (gc < NOUT)
                v = *reinterpret_cast<const float4*>(W + (size_t)(k0 + r) * NOUT + gc);
            *reinterpret_cast<float4*>(&Bs[r][c4 * 4]) = v;
        }
        __syncthreads();
#pragma unroll
        for (int kk = 0; kk < BK; kk++) {
            float a[8];
#pragma unroll
            for (int i = 0; i < 8; i++) a[i] = As[kk][ty * 8 + i];
            const float4 b = *reinterpret_cast<const float4*>(&Bs[kk][tx * 4]);
            const float bb[4] = {b.x, b.y, b.z, b.w};
#pragma unroll
            for (int i = 0; i < 8; i++)
#pragma unroll
                for (int j = 0; j < 4; j++) acc[i][j] += a[i] * bb[j];
        }
        __syncthreads();
    }

#pragma unroll
    for (int i = 0; i < 8; i++) {
        const int m = m0 + ty * 8 + i;
        if (m >= NNODES) continue;
        const int c0 = tx * 4;
        if (c0 + 3 < NOUT) {
            uint2 o;
            __half2* oh = reinterpret_cast<__half2*>(&o);
            oh[0] = __floats2half2_rn(acc[i][0], acc[i][1]);
            oh[1] = __floats2half2_rn(acc[i][2], acc[i][3]);
            *reinterpret_cast<uint2*>(C + (size_t)m * NOUT + c0) = o;
        }
    }
}

// ---------------- launch ----------------
// ATTRIBUTION ROUND: every aggregation launch is issued TWICE (idempotent).
// dur_delta vs previous round == total aggregation time.
extern "C" void kernel_launch(void* const* d_in, const int* in_sizes, int n_in,
                              void* d_out, int out_size) {
    const float* x = (const float*)d_in[0];
    const int* ei = (const int*)d_in[1];
    const float* W1 = (const float*)d_in[2];
    const float* b1 = (const float*)d_in[3];
    const float* W2 = (const float*)d_in[4];
    const float* b2 = (const float*)d_in[5];
    const float* W3 = (const float*)d_in[6];
    const float* b3 = (const float*)d_in[7];
    const float* W4 = (const float*)d_in[8];
    const float* b4 = (const float*)d_in[9];
    float* out = (float*)d_out;
    const int E = in_sizes[1] / 2;

    k_init<<<(NNODES + 255) / 256, 256>>>();
    k_hist<<<(E + 255) / 256, 256>>>(ei, E);
    k_scan<<<1, 1024>>>(NNODES, E);
    k_dinv<<<(NNODES + 255) / 256, 256>>>();
    k_scatter<<<(E + 255) / 256, 256>>>(ei, E);
    k_wconv<<<(256 * 256 + 255) / 256, 256>>>(W1, W2, W3);
    k_xconv<<<(NNODES * (FIN / 4) + 255) / 256, 256>>>(x, 1);

    const int AGG_BLOCKS = (NNODES + 7) / 8;
    const dim3 GM((NNODES + 63) / 64, 1);
    const dim3 G5((NNODES + 127) / 128, 1);

    // conv1 (agg doubled)
    k_agg_x_h<<<AGG_BLOCKS, 256>>>(1, 0);
    k_agg_x_h<<<AGG_BLOCKS, 256>>>(1, 0);
    k_gemm_mma<128, true><<<GM, 256>>>(0, 1, b1, 1);

    // conv2 (agg doubled)
    k_gemm_mma<256, false><<<GM, 256>>>(1, 2, nullptr, 0);
    k_agg_h256<<<AGG_BLOCKS, 256>>>(0, 1, b2);
    k_agg_h256<<<AGG_BLOCKS, 256>>>(0, 1, b2);

    // conv3 (agg doubled)
    k_gemm_mma<256, false><<<GM, 256>>>(1, 2, nullptr, 0);
    k_agg_h256<<<AGG_BLOCKS, 256>>>(0, 1, b2);
    k_agg_h256<<<AGG_BLOCKS, 256>>>(0, 1, b2);

    // conv4 (agg doubled)
    k_gemm_mma<256, false><<<GM, 256>>>(1, 3, nullptr, 0);
    k_agg_h256<<<AGG_BLOCKS, 256>>>(0, 1, b3);
    k_agg_h256<<<AGG_BLOCKS, 256>>>(0, 1, b3);

    // conv5 (agg doubled)
    k_gemm_small<<<G5, 256>>>(1, W4, 0);
    k_agg40_lsm<<<AGG_BLOCKS, 256>>>(0, out, b4);
    k_agg40_lsm<<<AGG_BLOCKS, 256>>>(0, out, b4);
}

// round 10
// speedup vs baseline: 2.0452x; 2.0452x over previous
#include <cuda_runtime.h>
#include <cuda_fp16.h>
#include <math.h>

#define NNODES 100000
#define NPAD   100096
#define FIN    128
#define HID    256
#define NCLS   40
#define EMAX   1600000
#define NBLK256 ((NNODES + 255) / 256)   // 391

// ---------------- scratch ----------------
__device__ __half g_bufA[(size_t)NPAD * HID];
__device__ __half g_bufB[(size_t)NPAD * HID];
__device__ __half g_W1T[256 * 128];
__device__ __half g_W2T[256 * 256];
__device__ __half g_W3T[256 * 256];
__device__ __half g_W4T[40 * 256];
__device__ float g_dinv[NNODES];
__device__ int   g_hist[NNODES];
__device__ int   g_rowptr[NNODES + 1];
__device__ int   g_fill[NNODES];
__device__ int   g_col[EMAX];
__device__ int   g_bsum[NBLK256];
__device__ int   g_boff[NBLK256];

__device__ __forceinline__ __half* selbuf(int s) { return s ? g_bufB : g_bufA; }

__device__ __forceinline__ void h8_to_f8(uint4 v, float* f) {
    const __half2* h = reinterpret_cast<const __half2*>(&v);
#pragma unroll
    for (int k = 0; k < 4; k++) {
        float2 t = __half22float2(h[k]);
        f[2 * k] = t.x;
        f[2 * k + 1] = t.y;
    }
}
__device__ __forceinline__ uint4 f8_to_h8(const float* f) {
    uint4 o;
    __half2* h = reinterpret_cast<__half2*>(&o);
#pragma unroll
    for (int k = 0; k < 4; k++) h[k] = __floats2half2_rn(f[2 * k], f[2 * k + 1]);
    return o;
}

// ---------------- precompute ----------------
__global__ void k_init() {
    int i = blockIdx.x * blockDim.x + threadIdx.x;
    if (i < NNODES) g_hist[i] = 0;
}

__global__ void k_hist(const int* __restrict__ ei, int E) {
    int e = blockIdx.x * blockDim.x + threadIdx.x;
    if (e < E) atomicAdd(&g_hist[ei[E + e]], 1);
}

// scan stage 1: per-block sums of g_hist
__global__ void k_scan_s1() {
    __shared__ int s[256];
    const int t = threadIdx.x;
    const int i = blockIdx.x * 256 + t;
    s[t] = (i < NNODES) ? g_hist[i] : 0;
    __syncthreads();
    for (int off = 128; off; off >>= 1) {
        if (t < off) s[t] += s[t + off];
        __syncthreads();
    }
    if (t == 0) g_bsum[blockIdx.x] = s[0];
}

// scan stage 2: exclusive scan of block sums (1 block, 512 threads)
__global__ void k_scan_s2() {
    __shared__ int s[512];
    const int t = threadIdx.x;
    s[t] = (t < NBLK256) ? g_bsum[t] : 0;
    __syncthreads();
    for (int off = 1; off < 512; off <<= 1) {
        int v = (t >= off) ? s[t - off] : 0;
        __syncthreads();
        s[t] += v;
        __syncthreads();
    }
    if (t < NBLK256) g_boff[t] = (t == 0) ? 0 : s[t - 1];
}

// scan stage 3: within-block exclusive scan + rowptr/fill + dinv
__global__ void k_scan_s3(int E) {
    __shared__ int s[256];
    const int t = threadIdx.x;
    const int i = blockIdx.x * 256 + t;
    const int h = (i < NNODES) ? g_hist[i] : 0;
    s[t] = h;
    __syncthreads();
    for (int off = 1; off < 256; off <<= 1) {
        int v = (t >= off) ? s[t - off] : 0;
        __syncthreads();
        s[t] += v;
        __syncthreads();
    }
    if (i < NNODES) {
        const int ex = g_boff[blockIdx.x] + s[t] - h;
        g_rowptr[i] = ex;
        g_fill[i] = ex;
        g_dinv[i] = rsqrtf((float)(h + 1));
    }
    if (i == 0) g_rowptr[NNODES] = E;
}

__global__ void k_scatter(const int* __restrict__ ei, int E) {
    int e = blockIdx.x * blockDim.x + threadIdx.x;
    if (e < E) {
        int d = ei[E + e];
        int pos = atomicAdd(&g_fill[d], 1);
        g_col[pos] = ei[e];
    }
}

// fp32 weights -> fp16 WT[n][k], k-permuted per 16-group for HMMA B frags
__global__ void k_wconv(const float* __restrict__ W1, const float* __restrict__ W2,
                        const float* __restrict__ W3, const float* __restrict__ W4) {
    int i = blockIdx.x * blockDim.x + threadIdx.x;
    if (i < 256 * 256) {
        int n = i >> 8, k = i & 255;
        int ko = (k & ~15) + 2 * ((k >> 2) & 3) + (k & 1) + (((k >> 1) & 1) << 3);
        g_W2T[n * 256 + k] = __float2half(W2[ko * 256 + n]);
        g_W3T[n * 256 + k] = __float2half(W3[ko * 256 + n]);
    }
    if (i < 256 * 128) {
        int n = i >> 7, k = i & 127;
        int ko = (k & ~15) + 2 * ((k >> 2) & 3) + (k & 1) + (((k >> 1) & 1) << 3);
        g_W1T[n * 128 + k] = __float2half(W1[ko * 256 + n]);
    }
    if (i < 40 * 256) {
        int n = i >> 8, k = i & 255;
        int ko = (k & ~15) + 2 * ((k >> 2) & 3) + (k & 1) + (((k >> 1) & 1) << 3);
        g_W4T[n * 256 + k] = __float2half(W4[ko * NCLS + n]);
    }
}

// x fp32 -> fp16
__global__ void k_xconv(const float* __restrict__ x, int dst_sel) {
    int i = blockIdx.x * blockDim.x + threadIdx.x;
    if (i < NNODES * (FIN / 4)) {
        float4 v = reinterpret_cast<const float4*>(x)[i];
        uint2 o;
        __half2* oh = reinterpret_cast<__half2*>(&o);
        oh[0] = __floats2half2_rn(v.x, v.y);
        oh[1] = __floats2half2_rn(v.z, v.w);
        reinterpret_cast<uint2*>(selbuf(dst_sel))[i] = o;
    }
}

// ---------------- agg conv1: gather fp16 (F=128) ----------------
__global__ void k_agg_x_h(int src_sel, int dst_sel) {
    const __half* in = selbuf(src_sel);
    __half* out = selbuf(dst_sel);
    const int wid = (blockIdx.x * blockDim.x + threadIdx.x) >> 5;
    if (wid >= NNODES) return;
    const int lane = threadIdx.x & 31;
    const int coff = lane * 4;

    float acc[4] = {0.f, 0.f, 0.f, 0.f};
    const int beg = g_rowptr[wid];
    const int end = g_rowptr[wid + 1];
    for (int base = beg; base < end; base += 32) {
        const int nrem = end - base;
        int idx = 0;
        float w = 0.f;
        if (lane < nrem) {
            idx = g_col[base + lane];
            w = g_dinv[idx];
        }
        const int m = nrem < 32 ? nrem : 32;
        int j = 0;
        for (; j + 2 <= m; j += 2) {
            const int s0 = __shfl_sync(0xffffffffu, idx, j);
            const int s1 = __shfl_sync(0xffffffffu, idx, j + 1);
            const float w0 = __shfl_sync(0xffffffffu, w, j);
            const float w1 = __shfl_sync(0xffffffffu, w, j + 1);
            uint2 v0 = *reinterpret_cast<const uint2*>(in + (size_t)s0 * FIN + coff);
            uint2 v1 = *reinterpret_cast<const uint2*>(in + (size_t)s1 * FIN + coff);
            const __half2* h0 = reinterpret_cast<const __half2*>(&v0);
            const __half2* h1 = reinterpret_cast<const __half2*>(&v1);
#pragma unroll
            for (int k = 0; k < 2; k++) {
                float2 a = __half22float2(h0[k]);
                float2 b = __half22float2(h1[k]);
                acc[2 * k] += w0 * a.x + w1 * b.x;
                acc[2 * k + 1] += w0 * a.y + w1 * b.y;
            }
        }
        for (; j < m; j++) {
            const int s = __shfl_sync(0xffffffffu, idx, j);
            const float ww = __shfl_sync(0xffffffffu, w, j);
            uint2 v = *reinterpret_cast<const uint2*>(in + (size_t)s * FIN + coff);
            const __half2* h = reinterpret_cast<const __half2*>(&v);
#pragma unroll
            for (int k = 0; k < 2; k++) {
                float2 a = __half22float2(h[k]);
                acc[2 * k] += ww * a.x;
                acc[2 * k + 1] += ww * a.y;
            }
        }
    }
    const float di = g_dinv[wid];
    {
        uint2 v = *reinterpret_cast<const uint2*>(in + (size_t)wid * FIN + coff);
        const __half2* h = reinterpret_cast<const __half2*>(&v);
#pragma unroll
        for (int k = 0; k < 2; k++) {
            float2 a = __half22float2(h[k]);
            acc[2 * k] += di * a.x;
            acc[2 * k + 1] += di * a.y;
        }
    }
    uint2 o;
    __half2* oh = reinterpret_cast<__half2*>(&o);
    oh[0] = __floats2half2_rn(di * acc[0], di * acc[1]);
    oh[1] = __floats2half2_rn(di * acc[2], di * acc[3]);
    *reinterpret_cast<uint2*>(out + (size_t)wid * FIN + coff) = o;
}

// ---------------- agg mid layers: gather half F=256, +bias+relu ----------------
__global__ void k_agg_h256(int src_sel, int dst_sel, const float* __restrict__ bias) {
    const __half* in = selbuf(src_sel);
    __half* out = selbuf(dst_sel);
    const int wid = (blockIdx.x * blockDim.x + threadIdx.x) >> 5;
    if (wid >= NNODES) return;
    const int lane = threadIdx.x & 31;
    const int coff = lane * 8;

    float acc[8];
#pragma unroll
    for (int i = 0; i < 8; i++) acc[i] = 0.f;

    const int beg = g_rowptr[wid];
    const int end = g_rowptr[wid + 1];
    for (int base = beg; base < end; base += 32) {
        const int nrem = end - base;
        int idx = 0;
        float w = 0.f;
        if (lane < nrem) {
            idx = g_col[base + lane];
            w = g_dinv[idx];
        }
        const int m = nrem < 32 ? nrem : 32;
        int j = 0;
        for (; j + 2 <= m; j += 2) {
            const int s0 = __shfl_sync(0xffffffffu, idx, j);
            const int s1 = __shfl_sync(0xffffffffu, idx, j + 1);
            const float w0 = __shfl_sync(0xffffffffu, w, j);
            const float w1 = __shfl_sync(0xffffffffu, w, j + 1);
            uint4 v0 = *reinterpret_cast<const uint4*>(in + (size_t)s0 * HID + coff);
            uint4 v1 = *reinterpret_cast<const uint4*>(in + (size_t)s1 * HID + coff);
            float f0[8], f1[8];
            h8_to_f8(v0, f0);
            h8_to_f8(v1, f1);
#pragma unroll
            for (int i = 0; i < 8; i++) acc[i] += w0 * f0[i] + w1 * f1[i];
        }
        for (; j < m; j++) {
            const int s = __shfl_sync(0xffffffffu, idx, j);
            const float ww = __shfl_sync(0xffffffffu, w, j);
            uint4 v = *reinterpret_cast<const uint4*>(in + (size_t)s * HID + coff);
            float f[8];
            h8_to_f8(v, f);
#pragma unroll
            for (int i = 0; i < 8; i++) acc[i] += ww * f[i];
        }
    }
    const float di = g_dinv[wid];
    {
        uint4 v = *reinterpret_cast<const uint4*>(in + (size_t)wid * HID + coff);
        float f[8];
        h8_to_f8(v, f);
#pragma unroll
        for (int i = 0; i < 8; i++) acc[i] += di * f[i];
    }
    float r[8];
#pragma unroll
    for (int i = 0; i < 8; i++) {
        r[i] = fmaxf(di * acc[i] + bias[coff + i], 0.f);
    }
    *reinterpret_cast<uint4*>(out + (size_t)wid * HID + coff) = f8_to_h8(r);
}

// ---------------- final: gather half F=40, +bias, log_softmax ----------------
__global__ void k_agg40_lsm(int src_sel, float* __restrict__ out,
                            const float* __restrict__ bias) {
    const __half* in = selbuf(src_sel);
    const int wid = (blockIdx.x * blockDim.x + threadIdx.x) >> 5;
    if (wid >= NNODES) return;
    const int lane = threadIdx.x & 31;
    const bool has2 = lane < (NCLS - 32);

    float a0 = 0.f, a1 = 0.f;
    const int beg = g_rowptr[wid];
    const int end = g_rowptr[wid + 1];
    for (int base = beg; base < end; base += 32) {
        const int nrem = end - base;
        int idx = 0;
        float w = 0.f;
        if (lane < nrem) {
            idx = g_col[base + lane];
            w = g_dinv[idx];
        }
        const int m = nrem < 32 ? nrem : 32;
        for (int j = 0; j < m; j++) {
            const int s = __shfl_sync(0xffffffffu, idx, j);
            const float ww = __shfl_sync(0xffffffffu, w, j);
            a0 += ww * __half2float(in[(size_t)s * NCLS + lane]);
            if (has2) a1 += ww * __half2float(in[(size_t)s * NCLS + 32 + lane]);
        }
    }
    const float di = g_dinv[wid];
    a0 += di * __half2float(in[(size_t)wid * NCLS + lane]);
    if (has2) a1 += di * __half2float(in[(size_t)wid * NCLS + 32 + lane]);

    a0 = di * a0 + bias[lane];
    a1 = has2 ? (di * a1 + bias[32 + lane]) : -INFINITY;

    float mx = fmaxf(a0, a1);
#pragma unroll
    for (int off = 16; off; off >>= 1) mx = fmaxf(mx, __shfl_xor_sync(0xffffffffu, mx, off));
    float se = expf(a0 - mx) + (has2 ? expf(a1 - mx) : 0.f);
#pragma unroll
    for (int off = 16; off; off >>= 1) se += __shfl_xor_sync(0xffffffffu, se, off);
    const float lse = logf(se) + mx;

    out[(size_t)wid * NCLS + lane] = a0 - lse;
    if (has2) out[(size_t)wid * NCLS + 32 + lane] = a1 - lse;
}

// ---------------- smem-staged tensor-core GEMM ----------------
// Block 128M x 128N, 4 warps (2Mx2N), warp tile 64x64. BK=64 k-chunks in smem.
// A frags via ldmatrix.x4 (canonical = R7-validated order), B frags via LDS.64 from permuted WT.
template <int K, bool EPI>
__global__ __launch_bounds__(128) void k_gemm_mma2(int src_sel, int wsel,
                                                   const float* __restrict__ bias, int dst_sel) {
    const __half* A = selbuf(src_sel);
    __half* C = selbuf(dst_sel);
    const __half* WT = (wsel == 1) ? g_W1T : (wsel == 2) ? g_W2T : g_W3T;

    constexpr int BK = 64, LDSW = BK + 8;   // 72 halfs (144B) row stride
    __shared__ __half As[128][LDSW];
    __shared__ __half Bs[128][LDSW];

    const int tid = threadIdx.x;
    const int wid = tid >> 5;
    const int lane = tid & 31;
    const int gid = lane >> 2;
    const int tig = lane & 3;
    const int m0 = blockIdx.x * 128;
    const int n0 = blockIdx.y * 128;
    const int mb = (wid & 1) * 64;
    const int nb = (wid >> 1) * 64;

    float c[4][8][4];
#pragma unroll
    for (int i = 0; i < 4; i++)
#pragma unroll
        for (int j = 0; j < 8; j++)
#pragma unroll
            for (int q = 0; q < 4; q++) c[i][j][q] = 0.f;

    for (int kc = 0; kc < K; kc += BK) {
        if (kc) __syncthreads();
#pragma unroll
        for (int l = 0; l < 8; l++) {
            const int idx = tid + l * 128;       // 0..1023
            const int r = idx >> 3;
            const int c16 = idx & 7;
            *reinterpret_cast<uint4*>(&As[r][c16 * 8]) =
                *reinterpret_cast<const uint4*>(A + (size_t)(m0 + r) * K + kc + c16 * 8);
            *reinterpret_cast<uint4*>(&Bs[r][c16 * 8]) =
                *reinterpret_cast<const uint4*>(WT + (size_t)(n0 + r) * K + kc + c16 * 8);
        }
        __syncthreads();
#pragma unroll
        for (int kg = 0; kg < BK / 16; kg++) {
            const int kk = kg * 16;
            unsigned a[4][4];
#pragma unroll
            for (int i = 0; i < 4; i++) {
                unsigned addr = (unsigned)__cvta_generic_to_shared(
                    &As[mb + i * 16 + (lane & 15)][kk + (lane >> 4) * 8]);
                asm volatile("ldmatrix.sync.aligned.m8n8.x4.shared.b16 {%0,%1,%2,%3}, [%4];"
                             : "=r"(a[i][0]), "=r"(a[i][1]), "=r"(a[i][2]), "=r"(a[i][3])
                             : "r"(addr));
            }
#pragma unroll
            for (int j = 0; j < 8; j++) {
                const uint2 b = *reinterpret_cast<const uint2*>(&Bs[nb + j * 8 + gid][kk + tig * 4]);
#pragma unroll
                for (int i = 0; i < 4; i++) {
                    asm volatile(
                        "mma.sync.aligned.m16n8k16.row.col.f32.f16.f16.f32 "
                        "{%0,%1,%2,%3}, {%4,%5,%6,%7}, {%8,%9}, {%0,%1,%2,%3};"
                        : "+f"(c[i][j][0]), "+f"(c[i][j][1]), "+f"(c[i][j][2]), "+f"(c[i][j][3])
                        : "r"(a[i][0]), "r"(a[i][1]), "r"(a[i][2]), "r"(a[i][3]),
                          "r"(b.x), "r"(b.y));
                }
            }
        }
    }

#pragma unroll
    for (int i = 0; i < 4; i++) {
        const int r0 = m0 + mb + i * 16 + gid;
#pragma unroll
        for (int j = 0; j < 8; j++) {
            const int col = n0 + nb + j * 8 + 2 * tig;
            float v0 = c[i][j][0], v1 = c[i][j][1], v2 = c[i][j][2], v3 = c[i][j][3];
            if (EPI) {
                const float bz0 = bias[col];
                const float bz1 = bias[col + 1];
                v0 = fmaxf(v0 + bz0, 0.f); v1 = fmaxf(v1 + bz1, 0.f);
                v2 = fmaxf(v2 + bz0, 0.f); v3 = fmaxf(v3 + bz1, 0.f);
            }
            if (r0 < NNODES)
                *reinterpret_cast<__half2*>(C + (size_t)r0 * HID + col) = __floats2half2_rn(v0, v1);
            if (r0 + 8 < NNODES)
                *reinterpret_cast<__half2*>(C + (size_t)(r0 + 8) * HID + col) = __floats2half2_rn(v2, v3);
        }
    }
}

// ---------------- mma small GEMM: C_half[M,40] = A_half[M,256] @ W4 ----------------
// R7-style no-smem: 8 warps x 32 rows, 5 n-groups.
__global__ __launch_bounds__(256) void k_gemm_small_mma(int src_sel, int dst_sel) {
    const __half* A = selbuf(src_sel);
    __half* C = selbuf(dst_sel);
    constexpr int K = HID;

    const int tid = threadIdx.x;
    const int wid = tid >> 5;
    const int lane = tid & 31;
    const int gid = lane >> 2;
    const int tig = lane & 3;
    const int mbase = blockIdx.x * 256 + wid * 32;

    float c[2][5][4];
#pragma unroll
    for (int i = 0; i < 2; i++)
#pragma unroll
        for (int j = 0; j < 5; j++)
#pragma unroll
            for (int q = 0; q < 4; q++) c[i][j][q] = 0.f;

#pragma unroll 4
    for (int kg = 0; kg < K / 16; kg++) {
        const int k0 = kg * 16;
        unsigned a[2][4];
#pragma unroll
        for (int i = 0; i < 2; i++) {
            const __half* ap = A + (size_t)(mbase + i * 16 + gid) * K + k0 + 2 * tig;
            a[i][0] = *reinterpret_cast<const unsigned*>(ap);
            a[i][1] = *reinterpret_cast<const unsigned*>(ap + 8 * K);
            a[i][2] = *reinterpret_cast<const unsigned*>(ap + 8);
            a[i][3] = *reinterpret_cast<const unsigned*>(ap + 8 * K + 8);
        }
#pragma unroll
        for (int j = 0; j < 5; j++) {
            const uint2 b = *reinterpret_cast<const uint2*>(
                g_W4T + (size_t)(j * 8 + gid) * K + k0 + tig * 4);
#pragma unroll
            for (int i = 0; i < 2; i++) {
                asm volatile(
                    "mma.sync.aligned.m16n8k16.row.col.f32.f16.f16.f32 "
                    "{%0,%1,%2,%3}, {%4,%5,%6,%7}, {%8,%9}, {%0,%1,%2,%3};"
                    : "+f"(c[i][j][0]), "+f"(c[i][j][1]), "+f"(c[i][j][2]), "+f"(c[i][j][3])
                    : "r"(a[i][0]), "r"(a[i][1]), "r"(a[i][2]), "r"(a[i][3]),
                      "r"(b.x), "r"(b.y));
            }
        }
    }

#pragma unroll
    for (int i = 0; i < 2; i++) {
        const int r0 = mbase + i * 16 + gid;
#pragma unroll
        for (int j = 0; j < 5; j++) {
            const int col = j * 8 + 2 * tig;
            if (r0 < NNODES)
                *reinterpret_cast<__half2*>(C + (size_t)r0 * NCLS + col) =
                    __floats2half2_rn(c[i][j][0], c[i][j][1]);
            if (r0 + 8 < NNODES)
                *reinterpret_cast<__half2*>(C + (size_t)(r0 + 8) * NCLS + col) =
                    __floats2half2_rn(c[i][j][2], c[i][j][3]);
        }
    }
}

// ---------------- launch ----------------
extern "C" void kernel_launch(void* const* d_in, const int* in_sizes, int n_in,
                              void* d_out, int out_size) {
    const float* x = (const float*)d_in[0];
    const int* ei = (const int*)d_in[1];
    const float* W1 = (const float*)d_in[2];
    const float* b1 = (const float*)d_in[3];
    const float* W2 = (const float*)d_in[4];
    const float* b2 = (const float*)d_in[5];
    const float* W3 = (const float*)d_in[6];
    const float* b3 = (const float*)d_in[7];
    const float* W4 = (const float*)d_in[8];
    const float* b4 = (const float*)d_in[9];
    float* out = (float*)d_out;
    const int E = in_sizes[1] / 2;

    k_init<<<NBLK256, 256>>>();
    k_hist<<<(E + 255) / 256, 256>>>(ei, E);
    k_scan_s1<<<NBLK256, 256>>>();
    k_scan_s2<<<1, 512>>>();
    k_scan_s3<<<NBLK256, 256>>>(E);
    k_scatter<<<(E + 255) / 256, 256>>>(ei, E);
    k_wconv<<<(256 * 256 + 255) / 256, 256>>>(W1, W2, W3, W4);
    k_xconv<<<(NNODES * (FIN / 4) + 255) / 256, 256>>>(x, 1);

    const int AGG_BLOCKS = (NNODES + 7) / 8;
    const dim3 GG(NPAD / 128, 2);          // 128x128 tiles over N=256
    const int GS = NPAD / 256;             // small gemm: 256 rows/block

    // conv1
    k_agg_x_h<<<AGG_BLOCKS, 256>>>(1, 0);                     // B -> A
    k_gemm_mma2<128, true><<<GG, 128>>>(0, 1, b1, 1);         // A -> B

    // conv2
    k_gemm_mma2<256, false><<<GG, 128>>>(1, 2, nullptr, 0);   // B -> A
    k_agg_h256<<<AGG_BLOCKS, 256>>>(0, 1, b2);                // A -> B

    // conv3 (reuses W2/b2)
    k_gemm_mma2<256, false><<<GG, 128>>>(1, 2, nullptr, 0);
    k_agg_h256<<<AGG_BLOCKS, 256>>>(0, 1, b2);

    // conv4
    k_gemm_mma2<256, false><<<GG, 128>>>(1, 3, nullptr, 0);
    k_agg_h256<<<AGG_BLOCKS, 256>>>(0, 1, b3);

    // conv5
    k_gemm_small_mma<<<GS, 256>>>(1, 0);                      // B -> A
    k_agg40_lsm<<<AGG_BLOCKS, 256>>>(0, out, b4);
}

// round 11
// speedup vs baseline: 2.1290x; 1.0410x over previous
#include <cuda_runtime.h>
#include <cuda_fp16.h>
#include <math.h>

#define NNODES 100000
#define NPAD   100096
#define FIN    128
#define HID    256
#define NCLS   40
#define EMAX   1600000
#define NBLK256 ((NNODES + 255) / 256)   // 391

// ---------------- scratch ----------------
__device__ __half g_bufA[(size_t)NPAD * HID];
__device__ __half g_bufB[(size_t)NPAD * HID];
__device__ __half g_W1T[256 * 128];
__device__ __half g_W2T[256 * 256];
__device__ __half g_W3T[256 * 256];
__device__ __half g_W4T[40 * 256];
__device__ float g_dinv[NNODES];
__device__ int   g_hist[NNODES];
__device__ int   g_rowptr[NNODES + 1];
__device__ int   g_fill[NNODES];
__device__ int   g_col[EMAX];
__device__ int   g_bsum[NBLK256];
__device__ int   g_boff[NBLK256];

__device__ __forceinline__ __half* selbuf(int s) { return s ? g_bufB : g_bufA; }

__device__ __forceinline__ void h8_to_f8(uint4 v, float* f) {
    const __half2* h = reinterpret_cast<const __half2*>(&v);
#pragma unroll
    for (int k = 0; k < 4; k++) {
        float2 t = __half22float2(h[k]);
        f[2 * k] = t.x;
        f[2 * k + 1] = t.y;
    }
}
__device__ __forceinline__ uint4 f8_to_h8(const float* f) {
    uint4 o;
    __half2* h = reinterpret_cast<__half2*>(&o);
#pragma unroll
    for (int k = 0; k < 4; k++) h[k] = __floats2half2_rn(f[2 * k], f[2 * k + 1]);
    return o;
}

// ---------------- precompute ----------------
__global__ void k_init() {
    int i = blockIdx.x * blockDim.x + threadIdx.x;
    if (i < NNODES) g_hist[i] = 0;
}

__global__ void k_hist(const int* __restrict__ ei, int E) {
    int e = blockIdx.x * blockDim.x + threadIdx.x;
    if (e < E) atomicAdd(&g_hist[ei[E + e]], 1);
}

__global__ void k_scan_s1() {
    __shared__ int s[256];
    const int t = threadIdx.x;
    const int i = blockIdx.x * 256 + t;
    s[t] = (i < NNODES) ? g_hist[i] : 0;
    __syncthreads();
    for (int off = 128; off; off >>= 1) {
        if (t < off) s[t] += s[t + off];
        __syncthreads();
    }
    if (t == 0) g_bsum[blockIdx.x] = s[0];
}

__global__ void k_scan_s2() {
    __shared__ int s[512];
    const int t = threadIdx.x;
    s[t] = (t < NBLK256) ? g_bsum[t] : 0;
    __syncthreads();
    for (int off = 1; off < 512; off <<= 1) {
        int v = (t >= off) ? s[t - off] : 0;
        __syncthreads();
        s[t] += v;
        __syncthreads();
    }
    if (t < NBLK256) g_boff[t] = (t == 0) ? 0 : s[t - 1];
}

__global__ void k_scan_s3(int E) {
    __shared__ int s[256];
    const int t = threadIdx.x;
    const int i = blockIdx.x * 256 + t;
    const int h = (i < NNODES) ? g_hist[i] : 0;
    s[t] = h;
    __syncthreads();
    for (int off = 1; off < 256; off <<= 1) {
        int v = (t >= off) ? s[t - off] : 0;
        __syncthreads();
        s[t] += v;
        __syncthreads();
    }
    if (i < NNODES) {
        const int ex = g_boff[blockIdx.x] + s[t] - h;
        g_rowptr[i] = ex;
        g_fill[i] = ex;
        g_dinv[i] = rsqrtf((float)(h + 1));
    }
    if (i == 0) g_rowptr[NNODES] = E;
}

__global__ void k_scatter(const int* __restrict__ ei, int E) {
    int e = blockIdx.x * blockDim.x + threadIdx.x;
    if (e < E) {
        int d = ei[E + e];
        int pos = atomicAdd(&g_fill[d], 1);
        g_col[pos] = ei[e];
    }
}

// fp32 weights -> fp16 WT[n][k], k-permuted per 16-group for HMMA B frags
__global__ void k_wconv(const float* __restrict__ W1, const float* __restrict__ W2,
                        const float* __restrict__ W3, const float* __restrict__ W4) {
    int i = blockIdx.x * blockDim.x + threadIdx.x;
    if (i < 256 * 256) {
        int n = i >> 8, k = i & 255;
        int ko = (k & ~15) + 2 * ((k >> 2) & 3) + (k & 1) + (((k >> 1) & 1) << 3);
        g_W2T[n * 256 + k] = __float2half(W2[ko * 256 + n]);
        g_W3T[n * 256 + k] = __float2half(W3[ko * 256 + n]);
    }
    if (i < 256 * 128) {
        int n = i >> 7, k = i & 127;
        int ko = (k & ~15) + 2 * ((k >> 2) & 3) + (k & 1) + (((k >> 1) & 1) << 3);
        g_W1T[n * 128 + k] = __float2half(W1[ko * 256 + n]);
    }
    if (i < 40 * 256) {
        int n = i >> 8, k = i & 255;
        int ko = (k & ~15) + 2 * ((k >> 2) & 3) + (k & 1) + (((k >> 1) & 1) << 3);
        g_W4T[n * 256 + k] = __float2half(W4[ko * NCLS + n]);
    }
}

__global__ void k_xconv(const float* __restrict__ x, int dst_sel) {
    int i = blockIdx.x * blockDim.x + threadIdx.x;
    if (i < NNODES * (FIN / 4)) {
        float4 v = reinterpret_cast<const float4*>(x)[i];
        uint2 o;
        __half2* oh = reinterpret_cast<__half2*>(&o);
        oh[0] = __floats2half2_rn(v.x, v.y);
        oh[1] = __floats2half2_rn(v.z, v.w);
        reinterpret_cast<uint2*>(selbuf(dst_sel))[i] = o;
    }
}

// ---------------- agg conv1: gather fp16 (F=128) ----------------
__global__ void k_agg_x_h(int src_sel, int dst_sel) {
    const __half* in = selbuf(src_sel);
    __half* out = selbuf(dst_sel);
    const int wid = (blockIdx.x * blockDim.x + threadIdx.x) >> 5;
    if (wid >= NNODES) return;
    const int lane = threadIdx.x & 31;
    const int coff = lane * 4;

    float acc[4] = {0.f, 0.f, 0.f, 0.f};
    const int beg = g_rowptr[wid];
    const int end = g_rowptr[wid + 1];
    for (int base = beg; base < end; base += 32) {
        const int nrem = end - base;
        int idx = 0;
        float w = 0.f;
        if (lane < nrem) {
            idx = g_col[base + lane];
            w = g_dinv[idx];
        }
        const int m = nrem < 32 ? nrem : 32;
        int j = 0;
        for (; j + 2 <= m; j += 2) {
            const int s0 = __shfl_sync(0xffffffffu, idx, j);
            const int s1 = __shfl_sync(0xffffffffu, idx, j + 1);
            const float w0 = __shfl_sync(0xffffffffu, w, j);
            const float w1 = __shfl_sync(0xffffffffu, w, j + 1);
            uint2 v0 = *reinterpret_cast<const uint2*>(in + (size_t)s0 * FIN + coff);
            uint2 v1 = *reinterpret_cast<const uint2*>(in + (size_t)s1 * FIN + coff);
            const __half2* h0 = reinterpret_cast<const __half2*>(&v0);
            const __half2* h1 = reinterpret_cast<const __half2*>(&v1);
#pragma unroll
            for (int k = 0; k < 2; k++) {
                float2 a = __half22float2(h0[k]);
                float2 b = __half22float2(h1[k]);
                acc[2 * k] += w0 * a.x + w1 * b.x;
                acc[2 * k + 1] += w0 * a.y + w1 * b.y;
            }
        }
        for (; j < m; j++) {
            const int s = __shfl_sync(0xffffffffu, idx, j);
            const float ww = __shfl_sync(0xffffffffu, w, j);
            uint2 v = *reinterpret_cast<const uint2*>(in + (size_t)s * FIN + coff);
            const __half2* h = reinterpret_cast<const __half2*>(&v);
#pragma unroll
            for (int k = 0; k < 2; k++) {
                float2 a = __half22float2(h[k]);
                acc[2 * k] += ww * a.x;
                acc[2 * k + 1] += ww * a.y;
            }
        }
    }
    const float di = g_dinv[wid];
    {
        uint2 v = *reinterpret_cast<const uint2*>(in + (size_t)wid * FIN + coff);
        const __half2* h = reinterpret_cast<const __half2*>(&v);
#pragma unroll
        for (int k = 0; k < 2; k++) {
            float2 a = __half22float2(h[k]);
            acc[2 * k] += di * a.x;
            acc[2 * k + 1] += di * a.y;
        }
    }
    uint2 o;
    __half2* oh = reinterpret_cast<__half2*>(&o);
    oh[0] = __floats2half2_rn(di * acc[0], di * acc[1]);
    oh[1] = __floats2half2_rn(di * acc[2], di * acc[3]);
    *reinterpret_cast<uint2*>(out + (size_t)wid * FIN + coff) = o;
}

// ---------------- agg mid layers: gather half F=256, +bias+relu ----------------
__global__ void k_agg_h256(int src_sel, int dst_sel, const float* __restrict__ bias) {
    const __half* in = selbuf(src_sel);
    __half* out = selbuf(dst_sel);
    const int wid = (blockIdx.x * blockDim.x + threadIdx.x) >> 5;
    if (wid >= NNODES) return;
    const int lane = threadIdx.x & 31;
    const int coff = lane * 8;

    float acc[8];
#pragma unroll
    for (int i = 0; i < 8; i++) acc[i] = 0.f;

    const int beg = g_rowptr[wid];
    const int end = g_rowptr[wid + 1];
    for (int base = beg; base < end; base += 32) {
        const int nrem = end - base;
        int idx = 0;
        float w = 0.f;
        if (lane < nrem) {
            idx = g_col[base + lane];
            w = g_dinv[idx];
        }
        const int m = nrem < 32 ? nrem : 32;
        int j = 0;
        for (; j + 2 <= m; j += 2) {
            const int s0 = __shfl_sync(0xffffffffu, idx, j);
            const int s1 = __shfl_sync(0xffffffffu, idx, j + 1);
            const float w0 = __shfl_sync(0xffffffffu, w, j);
            const float w1 = __shfl_sync(0xffffffffu, w, j + 1);
            uint4 v0 = *reinterpret_cast<const uint4*>(in + (size_t)s0 * HID + coff);
            uint4 v1 = *reinterpret_cast<const uint4*>(in + (size_t)s1 * HID + coff);
            float f0[8], f1[8];
            h8_to_f8(v0, f0);
            h8_to_f8(v1, f1);
#pragma unroll
            for (int i = 0; i < 8; i++) acc[i] += w0 * f0[i] + w1 * f1[i];
        }
        for (; j < m; j++) {
            const int s = __shfl_sync(0xffffffffu, idx, j);
            const float ww = __shfl_sync(0xffffffffu, w, j);
            uint4 v = *reinterpret_cast<const uint4*>(in + (size_t)s * HID + coff);
            float f[8];
            h8_to_f8(v, f);
#pragma unroll
            for (int i = 0; i < 8; i++) acc[i] += ww * f[i];
        }
    }
    const float di = g_dinv[wid];
    {
        uint4 v = *reinterpret_cast<const uint4*>(in + (size_t)wid * HID + coff);
        float f[8];
        h8_to_f8(v, f);
#pragma unroll
        for (int i = 0; i < 8; i++) acc[i] += di * f[i];
    }
    float r[8];
#pragma unroll
    for (int i = 0; i < 8; i++) {
        r[i] = fmaxf(di * acc[i] + bias[coff + i], 0.f);
    }
    *reinterpret_cast<uint4*>(out + (size_t)wid * HID + coff) = f8_to_h8(r);
}

// ---------------- final: gather half F=40, +bias, log_softmax ----------------
__global__ void k_agg40_lsm(int src_sel, float* __restrict__ out,
                            const float* __restrict__ bias) {
    const __half* in = selbuf(src_sel);
    const int wid = (blockIdx.x * blockDim.x + threadIdx.x) >> 5;
    if (wid >= NNODES) return;
    const int lane = threadIdx.x & 31;
    const bool has2 = lane < (NCLS - 32);

    float a0 = 0.f, a1 = 0.f;
    const int beg = g_rowptr[wid];
    const int end = g_rowptr[wid + 1];
    for (int base = beg; base < end; base += 32) {
        const int nrem = end - base;
        int idx = 0;
        float w = 0.f;
        if (lane < nrem) {
            idx = g_col[base + lane];
            w = g_dinv[idx];
        }
        const int m = nrem < 32 ? nrem : 32;
        for (int j = 0; j < m; j++) {
            const int s = __shfl_sync(0xffffffffu, idx, j);
            const float ww = __shfl_sync(0xffffffffu, w, j);
            a0 += ww * __half2float(in[(size_t)s * NCLS + lane]);
            if (has2) a1 += ww * __half2float(in[(size_t)s * NCLS + 32 + lane]);
        }
    }
    const float di = g_dinv[wid];
    a0 += di * __half2float(in[(size_t)wid * NCLS + lane]);
    if (has2) a1 += di * __half2float(in[(size_t)wid * NCLS + 32 + lane]);

    a0 = di * a0 + bias[lane];
    a1 = has2 ? (di * a1 + bias[32 + lane]) : -INFINITY;

    float mx = fmaxf(a0, a1);
#pragma unroll
    for (int off = 16; off; off >>= 1) mx = fmaxf(mx, __shfl_xor_sync(0xffffffffu, mx, off));
    float se = expf(a0 - mx) + (has2 ? expf(a1 - mx) : 0.f);
#pragma unroll
    for (int off = 16; off; off >>= 1) se += __shfl_xor_sync(0xffffffffu, se, off);
    const float lse = logf(se) + mx;

    out[(size_t)wid * NCLS + lane] = a0 - lse;
    if (has2) out[(size_t)wid * NCLS + 32 + lane] = a1 - lse;
}

// ---------------- pipelined smem tensor-core GEMM ----------------
// Block 128M x 128N, 256 threads, 8 warps (2M x 4N), warp tile 64x32.
// BK=64 chunk staged in smem; NEXT chunk LDG'd into registers during compute.
template <int K, bool EPI>
__global__ __launch_bounds__(256) void k_gemm_mma3(int src_sel, int wsel,
                                                   const float* __restrict__ bias, int dst_sel) {
    const __half* A = selbuf(src_sel);
    __half* C = selbuf(dst_sel);
    const __half* WT = (wsel == 1) ? g_W1T : (wsel == 2) ? g_W2T : g_W3T;

    constexpr int BK = 64, LDSW = BK + 8;   // 72 halfs per row
    constexpr int T = K / BK;
    __shared__ __half As[128][LDSW];
    __shared__ __half Bs[128][LDSW];

    const int tid = threadIdx.x;
    const int wid = tid >> 5;
    const int lane = tid & 31;
    const int gid = lane >> 2;
    const int tig = lane & 3;
    const int m0 = blockIdx.x * 128;
    const int n0 = blockIdx.y * 128;
    const int mb = (wid & 1) * 64;
    const int nb = (wid >> 1) * 32;

    // load mapping: chunk = 128 rows x 8 uint4; 256 threads x 4 loads each (for A and B)
    const int Lr = tid >> 1;            // base row pattern via idx = tid + l*256
    (void)Lr;

    float c[4][4][4];
#pragma unroll
    for (int i = 0; i < 4; i++)
#pragma unroll
        for (int j = 0; j < 4; j++)
#pragma unroll
            for (int q = 0; q < 4; q++) c[i][j][q] = 0.f;

    uint4 ra[4], rb[4];

    auto load_regs = [&](int t) {
        const int kc = t * BK;
#pragma unroll
        for (int l = 0; l < 4; l++) {
            const int idx = tid + l * 256;   // 0..1023
            const int r = idx >> 3;
            const int c8 = idx & 7;
            ra[l] = *reinterpret_cast<const uint4*>(A + (size_t)(m0 + r) * K + kc + c8 * 8);
            rb[l] = *reinterpret_cast<const uint4*>(WT + (size_t)(n0 + r) * K + kc + c8 * 8);
        }
    };
    auto store_smem = [&]() {
#pragma unroll
        for (int l = 0; l < 4; l++) {
            const int idx = tid + l * 256;
            const int r = idx >> 3;
            const int c8 = idx & 7;
            *reinterpret_cast<uint4*>(&As[r][c8 * 8]) = ra[l];
            *reinterpret_cast<uint4*>(&Bs[r][c8 * 8]) = rb[l];
        }
    };

    load_regs(0);
    store_smem();
    __syncthreads();

    for (int t = 0; t < T; t++) {
        if (t + 1 < T) load_regs(t + 1);
#pragma unroll
        for (int kg = 0; kg < BK / 16; kg++) {
            const int kk = kg * 16;
            unsigned a[4][4];
#pragma unroll
            for (int i = 0; i < 4; i++) {
                unsigned addr = (unsigned)__cvta_generic_to_shared(
                    &As[mb + i * 16 + (lane & 15)][kk + (lane >> 4) * 8]);
                asm volatile("ldmatrix.sync.aligned.m8n8.x4.shared.b16 {%0,%1,%2,%3}, [%4];"
                             : "=r"(a[i][0]), "=r"(a[i][1]), "=r"(a[i][2]), "=r"(a[i][3])
                             : "r"(addr));
            }
#pragma unroll
            for (int j = 0; j < 4; j++) {
                const uint2 b = *reinterpret_cast<const uint2*>(&Bs[nb + j * 8 + gid][kk + tig * 4]);
#pragma unroll
                for (int i = 0; i < 4; i++) {
                    asm volatile(
                        "mma.sync.aligned.m16n8k16.row.col.f32.f16.f16.f32 "
                        "{%0,%1,%2,%3}, {%4,%5,%6,%7}, {%8,%9}, {%0,%1,%2,%3};"
                        : "+f"(c[i][j][0]), "+f"(c[i][j][1]), "+f"(c[i][j][2]), "+f"(c[i][j][3])
                        : "r"(a[i][0]), "r"(a[i][1]), "r"(a[i][2]), "r"(a[i][3]),
                          "r"(b.x), "r"(b.y));
                }
            }
        }
        if (t + 1 < T) {
            __syncthreads();
            store_smem();
            __syncthreads();
        }
    }

#pragma unroll
    for (int i = 0; i < 4; i++) {
        const int r0 = m0 + mb + i * 16 + gid;
#pragma unroll
        for (int j = 0; j < 4; j++) {
            const int col = n0 + nb + j * 8 + 2 * tig;
            float v0 = c[i][j][0], v1 = c[i][j][1], v2 = c[i][j][2], v3 = c[i][j][3];
            if (EPI) {
                const float bz0 = bias[col];
                const float bz1 = bias[col + 1];
                v0 = fmaxf(v0 + bz0, 0.f); v1 = fmaxf(v1 + bz1, 0.f);
                v2 = fmaxf(v2 + bz0, 0.f); v3 = fmaxf(v3 + bz1, 0.f);
            }
            if (r0 < NNODES)
                *reinterpret_cast<__half2*>(C + (size_t)r0 * HID + col) = __floats2half2_rn(v0, v1);
            if (r0 + 8 < NNODES)
                *reinterpret_cast<__half2*>(C + (size_t)(r0 + 8) * HID + col) = __floats2half2_rn(v2, v3);
        }
    }
}

// ---------------- mma small GEMM: C_half[M,40] = A_half[M,256] @ W4 ----------------
__global__ __launch_bounds__(256) void k_gemm_small_mma(int src_sel, int dst_sel) {
    const __half* A = selbuf(src_sel);
    __half* C = selbuf(dst_sel);
    constexpr int K = HID;

    const int tid = threadIdx.x;
    const int wid = tid >> 5;
    const int lane = tid & 31;
    const int gid = lane >> 2;
    const int tig = lane & 3;
    const int mbase = blockIdx.x * 256 + wid * 32;

    float c[2][5][4];
#pragma unroll
    for (int i = 0; i < 2; i++)
#pragma unroll
        for (int j = 0; j < 5; j++)
#pragma unroll
            for (int q = 0; q < 4; q++) c[i][j][q] = 0.f;

#pragma unroll 4
    for (int kg = 0; kg < K / 16; kg++) {
        const int k0 = kg * 16;
        unsigned a[2][4];
#pragma unroll
        for (int i = 0; i < 2; i++) {
            const __half* ap = A + (size_t)(mbase + i * 16 + gid) * K + k0 + 2 * tig;
            a[i][0] = *reinterpret_cast<const unsigned*>(ap);
            a[i][1] = *reinterpret_cast<const unsigned*>(ap + 8 * K);
            a[i][2] = *reinterpret_cast<const unsigned*>(ap + 8);
            a[i][3] = *reinterpret_cast<const unsigned*>(ap + 8 * K + 8);
        }
#pragma unroll
        for (int j = 0; j < 5; j++) {
            const uint2 b = *reinterpret_cast<const uint2*>(
                g_W4T + (size_t)(j * 8 + gid) * K + k0 + tig * 4);
#pragma unroll
            for (int i = 0; i < 2; i++) {
                asm volatile(
                    "mma.sync.aligned.m16n8k16.row.col.f32.f16.f16.f32 "
                    "{%0,%1,%2,%3}, {%4,%5,%6,%7}, {%8,%9}, {%0,%1,%2,%3};"
                    : "+f"(c[i][j][0]), "+f"(c[i][j][1]), "+f"(c[i][j][2]), "+f"(c[i][j][3])
                    : "r"(a[i][0]), "r"(a[i][1]), "r"(a[i][2]), "r"(a[i][3]),
                      "r"(b.x), "r"(b.y));
            }
        }
    }

#pragma unroll
    for (int i = 0; i < 2; i++) {
        const int r0 = mbase + i * 16 + gid;
#pragma unroll
        for (int j = 0; j < 5; j++) {
            const int col = j * 8 + 2 * tig;
            if (r0 < NNODES)
                *reinterpret_cast<__half2*>(C + (size_t)r0 * NCLS + col) =
                    __floats2half2_rn(c[i][j][0], c[i][j][1]);
            if (r0 + 8 < NNODES)
                *reinterpret_cast<__half2*>(C + (size_t)(r0 + 8) * NCLS + col) =
                    __floats2half2_rn(c[i][j][2], c[i][j][3]);
        }
    }
}

// ---------------- launch ----------------
extern "C" void kernel_launch(void* const* d_in, const int* in_sizes, int n_in,
                              void* d_out, int out_size) {
    const float* x = (const float*)d_in[0];
    const int* ei = (const int*)d_in[1];
    const float* W1 = (const float*)d_in[2];
    const float* b1 = (const float*)d_in[3];
    const float* W2 = (const float*)d_in[4];
    const float* b2 = (const float*)d_in[5];
    const float* W3 = (const float*)d_in[6];
    const float* b3 = (const float*)d_in[7];
    const float* W4 = (const float*)d_in[8];
    const float* b4 = (const float*)d_in[9];
    float* out = (float*)d_out;
    const int E = in_sizes[1] / 2;

    k_init<<<NBLK256, 256>>>();
    k_hist<<<(E + 255) / 256, 256>>>(ei, E);
    k_scan_s1<<<NBLK256, 256>>>();
    k_scan_s2<<<1, 512>>>();
    k_scan_s3<<<NBLK256, 256>>>(E);
    k_scatter<<<(E + 255) / 256, 256>>>(ei, E);
    k_wconv<<<(256 * 256 + 255) / 256, 256>>>(W1, W2, W3, W4);
    k_xconv<<<(NNODES * (FIN / 4) + 255) / 256, 256>>>(x, 1);

    const int AGG_BLOCKS = (NNODES + 7) / 8;
    const dim3 GG(NPAD / 128, 2);
    const int GS = NPAD / 256;

    // conv1
    k_agg_x_h<<<AGG_BLOCKS, 256>>>(1, 0);                     // B -> A
    k_gemm_mma3<128, true><<<GG, 256>>>(0, 1, b1, 1);         // A -> B

    // conv2
    k_gemm_mma3<256, false><<<GG, 256>>>(1, 2, nullptr, 0);   // B -> A
    k_agg_h256<<<AGG_BLOCKS, 256>>>(0, 1, b2);                // A -> B

    // conv3 (reuses W2/b2)
    k_gemm_mma3<256, false><<<GG, 256>>>(1, 2, nullptr, 0);
    k_agg_h256<<<AGG_BLOCKS, 256>>>(0, 1, b2);

    // conv4
    k_gemm_mma3<256, false><<<GG, 256>>>(1, 3, nullptr, 0);
    k_agg_h256<<<AGG_BLOCKS, 256>>>(0, 1, b3);

    // conv5
    k_gemm_small_mma<<<GS, 256>>>(1, 0);                      // B -> A
    k_agg40_lsm<<<AGG_BLOCKS, 256>>>(0, out, b4);
}